// round 11
// baseline (speedup 1.0000x reference)
#include <cuda_runtime.h>
#include <cstdint>

#define NMAX 8192
#define D 256
#define KP8 768                // int8 2-limb: A'=[a0|a1|a0], B'=[b0|b0|b1]
#define MARGIN 0.2f
#define FULLW 0xFFFFFFFFu

// ---------------------------------------------------------------------------
// Scratch (allocation-free rule: __device__ globals)
// ---------------------------------------------------------------------------
__device__ float g_diag[NMAX];
__device__ int   g_rank1[NMAX];
__device__ int   g_rank2[NMAX];
__device__ int   g_rowcost[NMAX];    // float bits, values >= 0
__device__ int   g_colcost[NMAX];    // float bits, values >= 0
__device__ float g_invSa[NMAX];      // vmax/127 per im row
__device__ float g_invSb[NMAX];      // vmax/127 per s row
__device__ signed char g_A8[NMAX * KP8];   // 6.3 MB
__device__ signed char g_B8[NMAX * KP8];   // 6.3 MB

// ---------------------------------------------------------------------------
// helpers
// ---------------------------------------------------------------------------
__device__ __forceinline__ uint32_t smem_u32(const void* p) {
    uint32_t a;
    asm("{ .reg .u64 t; cvta.to.shared.u64 t, %1; cvt.u32.u64 %0, t; }"
        : "=r"(a) : "l"(p));
    return a;
}
__device__ __forceinline__ void cp16(uint32_t dst, const void* src) {
    asm volatile("cp.async.cg.shared.global [%0], [%1], 16;"
                 :: "r"(dst), "l"(src));
}
__device__ __forceinline__ void mma_s8(int* d, const uint32_t* a, const uint32_t* b) {
    asm volatile(
        "mma.sync.aligned.m16n8k32.row.col.s32.s8.s8.s32 "
        "{%0,%1,%2,%3}, {%4,%5,%6,%7}, {%8,%9}, {%0,%1,%2,%3};"
        : "+r"(d[0]), "+r"(d[1]), "+r"(d[2]), "+r"(d[3])
        : "r"(a[0]), "r"(a[1]), "r"(a[2]), "r"(a[3]), "r"(b[0]), "r"(b[1]));
}

// ---------------------------------------------------------------------------
// init: zero scratch + output
// ---------------------------------------------------------------------------
__global__ void init_kernel(float* out, int n) {
    int i = blockIdx.x * blockDim.x + threadIdx.x;
    if (i < n) {
        g_rank1[i] = 0; g_rank2[i] = 0;
        g_rowcost[i] = 0; g_colcost[i] = 0;
    }
    if (i == 0) out[0] = 0.0f;
}

// ---------------------------------------------------------------------------
// quant: per-row scale S = 127/max|x|; a0 = rint(x*S), a1 = rint((x*S-a0)*254)
// A' = [a0 | a1 | a0], B' = [b0 | b0 | b1]
// One warp per row (handles both im and s rows of same index).
// ---------------------------------------------------------------------------
__device__ __forceinline__ uint32_t pack4(int q0, int q1, int q2, int q3) {
    return (uint32_t)(q0 & 0xFF) | ((uint32_t)(q1 & 0xFF) << 8) |
           ((uint32_t)(q2 & 0xFF) << 16) | ((uint32_t)(q3 & 0xFF) << 24);
}

__device__ __forceinline__ void quant_row(const float* src, signed char* dstrow,
                                          float* invS, int lane, int sec_hi2,
                                          int sec_lo) {
    // each lane owns 8 consecutive floats
    float v[8];
    const float4* s4 = (const float4*)(src);
    float4 x0 = s4[lane * 2], x1 = s4[lane * 2 + 1];
    v[0]=x0.x; v[1]=x0.y; v[2]=x0.z; v[3]=x0.w;
    v[4]=x1.x; v[5]=x1.y; v[6]=x1.z; v[7]=x1.w;
    float vmax = 1e-30f;
#pragma unroll
    for (int j = 0; j < 8; j++) vmax = fmaxf(vmax, fabsf(v[j]));
#pragma unroll
    for (int o = 16; o > 0; o >>= 1)
        vmax = fmaxf(vmax, __shfl_xor_sync(FULLW, vmax, o));
    const float S = 127.0f / vmax;
    if (lane == 0) *invS = vmax * (1.0f / 127.0f);
    int q0[8], q1[8];
#pragma unroll
    for (int j = 0; j < 8; j++) {
        float xs = v[j] * S;
        q0[j] = __float2int_rn(xs);
        q1[j] = __float2int_rn((xs - (float)q0[j]) * 254.0f);
    }
    uint2 w0 = make_uint2(pack4(q0[0],q0[1],q0[2],q0[3]), pack4(q0[4],q0[5],q0[6],q0[7]));
    uint2 w1 = make_uint2(pack4(q1[0],q1[1],q1[2],q1[3]), pack4(q1[4],q1[5],q1[6],q1[7]));
    *(uint2*)(dstrow + lane * 8)            = w0;   // section 0: limb0
    *(uint2*)(dstrow + 256 + lane * 8)      = (sec_hi2 ? w0 : w1);
    *(uint2*)(dstrow + 512 + lane * 8)      = (sec_lo  ? w1 : w0);
}

__global__ void quant_kernel(const float* __restrict__ im,
                             const float* __restrict__ s, int n) {
    int warp = (blockIdx.x * blockDim.x + threadIdx.x) >> 5;
    int lane = threadIdx.x & 31;
    if (warp >= n) return;
    // A: [a0 | a1 | a0]   (mid = limb1, last = limb0)
    quant_row(im + (size_t)warp * D, g_A8 + (size_t)warp * KP8,
              g_invSa + warp, lane, 0, 0);
    // B: [b0 | b0 | b1]   (mid = limb0, last = limb1)
    quant_row(s + (size_t)warp * D, g_B8 + (size_t)warp * KP8,
              g_invSb + warp, lane, 1, 1);
}

// ---------------------------------------------------------------------------
// diag_i = <im_i, s_i> in exact fp32, one warp per row
// ---------------------------------------------------------------------------
__global__ void diag_kernel(const float* __restrict__ im,
                            const float* __restrict__ s, int n) {
    int warp = (blockIdx.x * blockDim.x + threadIdx.x) >> 5;
    int lane = threadIdx.x & 31;
    if (warp >= n) return;
    const float4* a = (const float4*)(im + (size_t)warp * D);
    const float4* b = (const float4*)(s  + (size_t)warp * D);
    float acc = 0.0f;
#pragma unroll
    for (int k = lane; k < D / 4; k += 32) {
        float4 x = a[k], y = b[k];
        acc += x.x * y.x + x.y * y.y + x.z * y.z + x.w * y.w;
    }
#pragma unroll
    for (int o = 16; o > 0; o >>= 1) acc += __shfl_xor_sync(FULLW, acc, o);
    if (lane == 0) g_diag[warp] = acc;
}

// ---------------------------------------------------------------------------
// Fused IMMA int8 tile kernel: 128x128 score tile per CTA.
// 256 threads / 8 warps (4 M x 2 N), warp tile 32x64, m16n8k32.s8,
// K'=768 bytes, BK=64 bytes/stage, 12 stages (4 hi + 8 cross),
// double-buffered cp.async. Two int32 accumulator classes (hi, cross),
// combined in epilogue: v = (hi + cross/254) * invSa * invSb.
// ROWPAD=20 words: fragment LDS (20g+t) mod 32 -> 32 distinct banks.
// ---------------------------------------------------------------------------
#define BM 128
#define BN 128
#define BK 64                    // int8 bytes per row per stage
#define ROWPAD 20                // uint32 words per row (16 data + 4 pad)
#define NSTAGE (KP8 / BK)        // 12
#define NS_HI 4                  // stages 0..3 -> hi class; 4..11 -> cross
#define AS_WORDS (BM * ROWPAD)   // 2560 per stage
#define BS_WORDS (BN * ROWPAD)   // 2560 per stage
#define AS_OFF 0
#define BS_OFF (2 * AS_WORDS)                 // 5120
#define DIAGR_OFF (BS_OFF + 2 * BS_WORDS)     // 10240
#define DIAGC_OFF (DIAGR_OFF + 128)
#define INVA_OFF  (DIAGC_OFF + 128)
#define INVB_OFF  (INVA_OFF + 128)
#define RCNT_OFF  (INVB_OFF + 128)
#define RMAX_OFF  (RCNT_OFF + 128)
#define CCNT_OFF  (RMAX_OFF + 128)
#define CMAX_OFF  (CCNT_OFF + 128)
#define SMEM_WORDS (CMAX_OFF + 128)           // 11264
#define SMEM_BYTES (SMEM_WORDS * 4)           // 45056

// one pipeline stage: prefetch st+1, wait, compute into ACC
#define STAGE_BODY(ACC)                                                        \
    {                                                                          \
        const int cur = st & 1;                                                \
        if (st + 1 < NSTAGE) {                                                 \
            const int nxt = (st + 1) & 1;                                      \
            uint32_t adst = sb + (AS_OFF + nxt * AS_WORDS + ldrow * ROWPAD + ldch * 4) * 4; \
            uint32_t bdst = sb + (BS_OFF + nxt * BS_WORDS + ldrow * ROWPAD + ldch * 4) * 4; \
            const signed char* as = Abase + (st + 1) * BK;                     \
            const signed char* bs = Bbase + (st + 1) * BK;                     \
            cp16(adst,                        as);                             \
            cp16(adst + 64 * ROWPAD * 4,      as + (size_t)64 * KP8);          \
            cp16(bdst,                        bs);                             \
            cp16(bdst + 64 * ROWPAD * 4,      bs + (size_t)64 * KP8);          \
            asm volatile("cp.async.commit_group;");                            \
            asm volatile("cp.async.wait_group 1;");                            \
        } else {                                                               \
            asm volatile("cp.async.wait_group 0;");                            \
        }                                                                      \
        __syncthreads();                                                       \
        const uint32_t* As = smu + AS_OFF + cur * AS_WORDS;                    \
        const uint32_t* Bs = smu + BS_OFF + cur * BS_WORDS;                    \
        _Pragma("unroll")                                                      \
        for (int k32 = 0; k32 < 2; k32++) {                                    \
            uint32_t fa[2][4], fb[8][2];                                       \
            _Pragma("unroll")                                                  \
            for (int mt = 0; mt < 2; mt++) {                                   \
                const uint32_t* ap = As + (wm * 32 + mt * 16 + grp) * ROWPAD + k32 * 8 + tig; \
                fa[mt][0] = ap[0];                                             \
                fa[mt][1] = ap[8 * ROWPAD];                                    \
                fa[mt][2] = ap[4];                                             \
                fa[mt][3] = ap[8 * ROWPAD + 4];                                \
            }                                                                  \
            _Pragma("unroll")                                                  \
            for (int nt = 0; nt < 8; nt++) {                                   \
                const uint32_t* bp = Bs + (wn * 64 + nt * 8 + grp) * ROWPAD + k32 * 8 + tig; \
                fb[nt][0] = bp[0];                                             \
                fb[nt][1] = bp[4];                                             \
            }                                                                  \
            _Pragma("unroll")                                                  \
            for (int nt = 0; nt < 8; nt++)                                     \
                _Pragma("unroll")                                              \
                for (int mt = 0; mt < 2; mt++)                                 \
                    mma_s8(ACC[mt][nt], fa[mt], fb[nt]);                       \
        }                                                                      \
        __syncthreads();                                                       \
    }

__global__ __launch_bounds__(256, 1)
void tile_kernel() {
    extern __shared__ __align__(16) float smem[];
    uint32_t* smu = (uint32_t*)smem;
    int* sRCnt = (int*)(smem + RCNT_OFF);
    int* sRMax = (int*)(smem + RMAX_OFF);
    int* sCCnt = (int*)(smem + CCNT_OFF);
    int* sCMax = (int*)(smem + CMAX_OFF);

    const int tid  = threadIdx.x;
    const int wid  = tid >> 5;
    const int lane = tid & 31;
    const int wm   = wid >> 1;          // 0..3 -> M offset wm*32
    const int wn   = wid & 1;           // 0..1 -> N offset wn*64
    const int grp  = lane >> 2;         // 0..7
    const int tig  = lane & 3;          // 0..3
    const int i0 = blockIdx.y * BM;
    const int j0 = blockIdx.x * BN;
    const uint32_t sb = smem_u32(smem);

    if (tid < 128) {
        smem[DIAGR_OFF + tid] = g_diag[i0 + tid];
        smem[DIAGC_OFF + tid] = g_diag[j0 + tid];
        smem[INVA_OFF + tid]  = g_invSa[i0 + tid];
        smem[INVB_OFF + tid]  = g_invSb[j0 + tid];
        sRCnt[tid] = 0; sRMax[tid] = 0;
        sCCnt[tid] = 0; sCMax[tid] = 0;
    }

    int acc_hi[2][8][4], acc_x[2][8][4];
#pragma unroll
    for (int mt = 0; mt < 2; mt++)
#pragma unroll
        for (int nt = 0; nt < 8; nt++)
#pragma unroll
            for (int e = 0; e < 4; e++) { acc_hi[mt][nt][e] = 0; acc_x[mt][nt][e] = 0; }

    // staging: 64B/row/stage = 4 x 16B chunks; 128 rows x 4 ch = 512 tasks,
    // each thread does 2 for A and 2 for B (rows tid>>2 and tid>>2 + 64)
    const int ldrow = tid >> 2;          // 0..63 base row
    const int ldch  = tid & 3;           // 16B chunk within the 64B row-stage
    const signed char* Abase = g_A8 + (size_t)(i0 + ldrow) * KP8 + ldch * 16;
    const signed char* Bbase = g_B8 + (size_t)(j0 + ldrow) * KP8 + ldch * 16;
    __syncthreads();

    // ---- prologue: stage 0 ----
    {
        uint32_t adst = sb + (AS_OFF + ldrow * ROWPAD + ldch * 4) * 4;
        uint32_t bdst = sb + (BS_OFF + ldrow * ROWPAD + ldch * 4) * 4;
        cp16(adst,                   Abase);
        cp16(adst + 64 * ROWPAD * 4, Abase + (size_t)64 * KP8);
        cp16(bdst,                   Bbase);
        cp16(bdst + 64 * ROWPAD * 4, Bbase + (size_t)64 * KP8);
        asm volatile("cp.async.commit_group;");
    }

    for (int st = 0; st < NS_HI; st++)       STAGE_BODY(acc_hi)
    for (int st = NS_HI; st < NSTAGE; st++)  STAGE_BODY(acc_x)

    // ---- epilogue: v = (hi + cross/254) * invSa[row] * invSb[col] ----
    // Row stats: thread's rows = i0 + wm*32 + mt*16 + grp + h*8
#pragma unroll
    for (int mt = 0; mt < 2; mt++) {
#pragma unroll
        for (int h = 0; h < 2; h++) {
            const int rin = wm * 32 + mt * 16 + grp + h * 8;
            const int gi = i0 + rin;
            const float dr = smem[DIAGR_OFF + rin];
            const float ia = smem[INVA_OFF + rin];
            int cnt = 0;
            float rmax = 0.0f;
#pragma unroll
            for (int nt = 0; nt < 8; nt++) {
#pragma unroll
                for (int e = 0; e < 2; e++) {
                    const int cin = wn * 64 + nt * 8 + 2 * tig + e;
                    float v = ((float)acc_hi[mt][nt][h * 2 + e] +
                               (float)acc_x[mt][nt][h * 2 + e] * (1.0f / 254.0f))
                              * ia * smem[INVB_OFF + cin];
                    bool od = (gi != j0 + cin);
                    cnt += (od && (v < dr));
                    if (od) rmax = fmaxf(rmax, (MARGIN + v) - dr);
                }
            }
            cnt  += __shfl_xor_sync(FULLW, cnt, 1);
            rmax  = fmaxf(rmax, __shfl_xor_sync(FULLW, rmax, 1));
            cnt  += __shfl_xor_sync(FULLW, cnt, 2);
            rmax  = fmaxf(rmax, __shfl_xor_sync(FULLW, rmax, 2));
            if (tig == 0) {
                atomicAdd(&sRCnt[rin], cnt);
                atomicMax(&sRMax[rin], __float_as_int(rmax));
            }
        }
    }
    // Col stats: thread's cols = j0 + wn*64 + nt*8 + 2*tig + e
#pragma unroll
    for (int nt = 0; nt < 8; nt++) {
#pragma unroll
        for (int e = 0; e < 2; e++) {
            const int cin = wn * 64 + nt * 8 + 2 * tig + e;
            const float dc = smem[DIAGC_OFF + cin];
            const float ib = smem[INVB_OFF + cin];
            int cnt = 0;
            float cmax = 0.0f;
#pragma unroll
            for (int mt = 0; mt < 2; mt++) {
#pragma unroll
                for (int h = 0; h < 2; h++) {
                    const int rin = wm * 32 + mt * 16 + grp + h * 8;
                    const int gi = i0 + rin;
                    float v = ((float)acc_hi[mt][nt][h * 2 + e] +
                               (float)acc_x[mt][nt][h * 2 + e] * (1.0f / 254.0f))
                              * smem[INVA_OFF + rin] * ib;
                    bool od = (gi != j0 + cin);
                    cnt += (od && (v < dc));
                    if (od) cmax = fmaxf(cmax, (MARGIN + v) - dc);
                }
            }
            cnt  += __shfl_xor_sync(FULLW, cnt, 4);
            cmax  = fmaxf(cmax, __shfl_xor_sync(FULLW, cmax, 4));
            cnt  += __shfl_xor_sync(FULLW, cnt, 8);
            cmax  = fmaxf(cmax, __shfl_xor_sync(FULLW, cmax, 8));
            cnt  += __shfl_xor_sync(FULLW, cnt, 16);
            cmax  = fmaxf(cmax, __shfl_xor_sync(FULLW, cmax, 16));
            if (grp == 0) {
                atomicAdd(&sCCnt[cin], cnt);
                atomicMax(&sCMax[cin], __float_as_int(cmax));
            }
        }
    }
    __syncthreads();

    if (tid < 128) {
        atomicAdd(&g_rank1[i0 + tid], sRCnt[tid]);
        atomicMax(&g_rowcost[i0 + tid], sRMax[tid]);
        atomicAdd(&g_rank2[j0 + tid], sCCnt[tid]);
        atomicMax(&g_colcost[j0 + tid], sCMax[tid]);
    }
}

// ---------------------------------------------------------------------------
// Deterministic final reduction
// ---------------------------------------------------------------------------
__global__ void final_kernel(float* out, int n) {
    __shared__ float red[32];
    const int t = threadIdx.x;
    const int nv = n / 4;
    float sum = 0.0f;
#pragma unroll
    for (int v = 0; v < 2; v++) {
        int i = t + v * 1024;
        if (i < nv) {
            int4 r1 = ((const int4*)g_rank1)[i];
            int4 r2 = ((const int4*)g_rank2)[i];
            int4 rc = ((const int4*)g_rowcost)[i];
            int4 cc = ((const int4*)g_colcost)[i];
            sum += __int_as_float(rc.x) / ((float)r1.x + 1.0f)
                 + __int_as_float(rc.y) / ((float)r1.y + 1.0f)
                 + __int_as_float(rc.z) / ((float)r1.z + 1.0f)
                 + __int_as_float(rc.w) / ((float)r1.w + 1.0f)
                 + __int_as_float(cc.x) / ((float)r2.x + 1.0f)
                 + __int_as_float(cc.y) / ((float)r2.y + 1.0f)
                 + __int_as_float(cc.z) / ((float)r2.z + 1.0f)
                 + __int_as_float(cc.w) / ((float)r2.w + 1.0f);
        }
    }
#pragma unroll
    for (int o = 16; o > 0; o >>= 1) sum += __shfl_xor_sync(FULLW, sum, o);
    if ((t & 31) == 0) red[t >> 5] = sum;
    __syncthreads();
    if (t < 32) {
        float v = red[t];
#pragma unroll
        for (int o = 16; o > 0; o >>= 1) v += __shfl_xor_sync(FULLW, v, o);
        if (t == 0) out[0] = v;
    }
}

// ---------------------------------------------------------------------------
extern "C" void kernel_launch(void* const* d_in, const int* in_sizes, int n_in,
                              void* d_out, int out_size) {
    const float* im = (const float*)d_in[0];
    const float* s  = (const float*)d_in[1];
    float* out = (float*)d_out;
    const int n = in_sizes[0] / D;   // 8192

    cudaFuncSetAttribute(tile_kernel,
                         cudaFuncAttributeMaxDynamicSharedMemorySize, SMEM_BYTES);

    init_kernel<<<(n + 255) / 256, 256>>>(out, n);
    quant_kernel<<<(n * 32 + 255) / 256, 256>>>(im, s, n);
    diag_kernel<<<(n * 32 + 255) / 256, 256>>>(im, s, n);
    dim3 grid(n / BN, n / BM);
    tile_kernel<<<grid, 256, SMEM_BYTES>>>();
    final_kernel<<<1, 1024>>>(out, n);
}

// round 12
// speedup vs baseline: 5.7509x; 5.7509x over previous
#include <cuda_runtime.h>
#include <cuda_fp16.h>
#include <cstdint>

#define NMAX 8192
#define D 256
#define MARGIN 0.2f
#define FULLW 0xFFFFFFFFu

// ---------------------------------------------------------------------------
// Scratch (allocation-free rule: __device__ globals)
// ---------------------------------------------------------------------------
__device__ float  g_diag[NMAX];
__device__ int    g_rank1[NMAX];
__device__ int    g_rank2[NMAX];
__device__ int    g_rowcost[NMAX];   // float bits, values >= 0
__device__ int    g_colcost[NMAX];   // float bits, values >= 0
__device__ __half g_Ah[NMAX * D];    // 4.2 MB
__device__ __half g_Bh[NMAX * D];    // 4.2 MB

// ---------------------------------------------------------------------------
// helpers
// ---------------------------------------------------------------------------
__device__ __forceinline__ uint32_t smem_u32(const void* p) {
    uint32_t a;
    asm("{ .reg .u64 t; cvta.to.shared.u64 t, %1; cvt.u32.u64 %0, t; }"
        : "=r"(a) : "l"(p));
    return a;
}
__device__ __forceinline__ void cp16(uint32_t dst, const void* src) {
    asm volatile("cp.async.cg.shared.global [%0], [%1], 16;"
                 :: "r"(dst), "l"(src));
}
__device__ __forceinline__ void mma_f16(float* d, const uint32_t* a, const uint32_t* b) {
    asm volatile(
        "mma.sync.aligned.m16n8k16.row.col.f32.f16.f16.f32 "
        "{%0,%1,%2,%3}, {%4,%5,%6,%7}, {%8,%9}, {%0,%1,%2,%3};"
        : "+f"(d[0]), "+f"(d[1]), "+f"(d[2]), "+f"(d[3])
        : "r"(a[0]), "r"(a[1]), "r"(a[2]), "r"(a[3]), "r"(b[0]), "r"(b[1]));
}
__device__ __forceinline__ uint32_t h2pack(float x, float y) {
    __half2 h = __floats2half2_rn(x, y);
    return *(uint32_t*)&h;
}

// ---------------------------------------------------------------------------
// init: zero scratch + output
// ---------------------------------------------------------------------------
__global__ void init_kernel(float* out, int n) {
    int i = blockIdx.x * blockDim.x + threadIdx.x;
    if (i < n) {
        g_rank1[i] = 0; g_rank2[i] = 0;
        g_rowcost[i] = 0; g_colcost[i] = 0;
    }
    if (i == 0) out[0] = 0.0f;
}

// ---------------------------------------------------------------------------
// convert: plain fp16 (single section; error transfer measured tiny in R11)
// ---------------------------------------------------------------------------
__global__ void conv_kernel(const float* __restrict__ im, const float* __restrict__ s) {
    int g = blockIdx.x * blockDim.x + threadIdx.x;   // 0 .. 8192*64-1
    size_t idx = (size_t)g * 4;
    float4 a = *(const float4*)(im + idx);
    *(uint2*)(g_Ah + idx) = make_uint2(h2pack(a.x, a.y), h2pack(a.z, a.w));
    float4 b = *(const float4*)(s + idx);
    *(uint2*)(g_Bh + idx) = make_uint2(h2pack(b.x, b.y), h2pack(b.z, b.w));
}

// ---------------------------------------------------------------------------
// diag_i = <im_i, s_i> in exact fp32, one warp per row
// ---------------------------------------------------------------------------
__global__ void diag_kernel(const float* __restrict__ im,
                            const float* __restrict__ s, int n) {
    int warp = (blockIdx.x * blockDim.x + threadIdx.x) >> 5;
    int lane = threadIdx.x & 31;
    if (warp >= n) return;
    const float4* a = (const float4*)(im + (size_t)warp * D);
    const float4* b = (const float4*)(s  + (size_t)warp * D);
    float acc = 0.0f;
#pragma unroll
    for (int k = lane; k < D / 4; k += 32) {
        float4 x = a[k], y = b[k];
        acc += x.x * y.x + x.y * y.y + x.z * y.z + x.w * y.w;
    }
#pragma unroll
    for (int o = 16; o > 0; o >>= 1) acc += __shfl_xor_sync(FULLW, acc, o);
    if (lane == 0) g_diag[warp] = acc;
}

// ---------------------------------------------------------------------------
// Fused mma.sync fp16 tile kernel: 128x128 score tile per CTA.
// 256 threads / 8 warps (4 M x 2 N), warp tile 32x64, m16n8k16,
// K=256 halves, BK=64 halves, 4 double-buffered cp.async stages.
// 2 CTAs/SM. ROWPAD=36 words: fragment LDS conflict-free.
// ---------------------------------------------------------------------------
#define BM 128
#define BN 128
#define BK 64                    // halves per row per stage (128 B)
#define ROWPAD 36                // uint32 words per row (32 data + 4 pad)
#define NSTAGE (D / BK)          // 4
#define AS_WORDS (BM * ROWPAD)   // 4608 per stage
#define BS_WORDS (BN * ROWPAD)   // 4608 per stage
#define AS_OFF 0
#define BS_OFF (2 * AS_WORDS)                 // 9216
#define DIAGR_OFF (BS_OFF + 2 * BS_WORDS)     // 18432
#define DIAGC_OFF (DIAGR_OFF + 128)
#define RCNT_OFF  (DIAGC_OFF + 128)
#define RMAX_OFF  (RCNT_OFF + 128)
#define CCNT_OFF  (RMAX_OFF + 128)
#define CMAX_OFF  (CCNT_OFF + 128)
#define SMEM_WORDS (CMAX_OFF + 128)           // 19200
#define SMEM_BYTES (SMEM_WORDS * 4)           // 76800

__global__ __launch_bounds__(256, 2)
void tile_kernel() {
    extern __shared__ __align__(16) float smem[];
    uint32_t* smu = (uint32_t*)smem;
    int* sRCnt = (int*)(smem + RCNT_OFF);
    int* sRMax = (int*)(smem + RMAX_OFF);
    int* sCCnt = (int*)(smem + CCNT_OFF);
    int* sCMax = (int*)(smem + CMAX_OFF);

    const int tid  = threadIdx.x;
    const int wid  = tid >> 5;
    const int lane = tid & 31;
    const int wm   = wid >> 1;          // 0..3 -> M offset wm*32
    const int wn   = wid & 1;           // 0..1 -> N offset wn*64
    const int grp  = lane >> 2;         // 0..7
    const int tig  = lane & 3;          // 0..3
    const int i0 = blockIdx.y * BM;
    const int j0 = blockIdx.x * BN;
    const uint32_t sb = smem_u32(smem);

    if (tid < 128) {
        smem[DIAGR_OFF + tid] = g_diag[i0 + tid];
        smem[DIAGC_OFF + tid] = g_diag[j0 + tid];
        sRCnt[tid] = 0; sRMax[tid] = 0;
        sCCnt[tid] = 0; sCMax[tid] = 0;
    }
    __syncthreads();

    float acc[2][8][4];
#pragma unroll
    for (int mt = 0; mt < 2; mt++)
#pragma unroll
        for (int nt = 0; nt < 8; nt++)
#pragma unroll
            for (int e = 0; e < 4; e++) acc[mt][nt][e] = 0.0f;

    // staging: 16B = 8 halves per cp.async; row stage = 64 halves = 8 chunks
    const int ldrow = tid >> 3;         // 0..31 base row
    const int ldch  = tid & 7;          // chunk within row
    const __half* Abase = g_Ah + (size_t)(i0 + ldrow) * D + ldch * 8;
    const __half* Bbase = g_Bh + (size_t)(j0 + ldrow) * D + ldch * 8;

    // ---- prologue: stage 0 ----
    {
        uint32_t adst = sb + (AS_OFF + ldrow * ROWPAD + ldch * 4) * 4;
        uint32_t bdst = sb + (BS_OFF + ldrow * ROWPAD + ldch * 4) * 4;
#pragma unroll
        for (int q = 0; q < 4; q++)      // A: 128 rows, 32 apart
            cp16(adst + q * 32 * ROWPAD * 4, Abase + (size_t)(q * 32) * D);
#pragma unroll
        for (int q = 0; q < 4; q++)      // B: 128 rows
            cp16(bdst + q * 32 * ROWPAD * 4, Bbase + (size_t)(q * 32) * D);
        asm volatile("cp.async.commit_group;");
    }

#pragma unroll
    for (int st = 0; st < NSTAGE; st++) {
        const int cur = st & 1;
        if (st + 1 < NSTAGE) {
            const int nxt = (st + 1) & 1;
            uint32_t adst = sb + (AS_OFF + nxt * AS_WORDS + ldrow * ROWPAD + ldch * 4) * 4;
            uint32_t bdst = sb + (BS_OFF + nxt * BS_WORDS + ldrow * ROWPAD + ldch * 4) * 4;
            const __half* as = Abase + (st + 1) * BK;
            const __half* bs = Bbase + (st + 1) * BK;
#pragma unroll
            for (int q = 0; q < 4; q++)
                cp16(adst + q * 32 * ROWPAD * 4, as + (size_t)(q * 32) * D);
#pragma unroll
            for (int q = 0; q < 4; q++)
                cp16(bdst + q * 32 * ROWPAD * 4, bs + (size_t)(q * 32) * D);
            asm volatile("cp.async.commit_group;");
            asm volatile("cp.async.wait_group 1;");
        } else {
            asm volatile("cp.async.wait_group 0;");
        }
        __syncthreads();

        const uint32_t* As = smu + AS_OFF + cur * AS_WORDS;
        const uint32_t* Bs = smu + BS_OFF + cur * BS_WORDS;
#pragma unroll
        for (int k16 = 0; k16 < BK / 16; k16++) {
            uint32_t fa[2][4], fb[8][2];
#pragma unroll
            for (int mt = 0; mt < 2; mt++) {
                const uint32_t* ap = As + (wm * 32 + mt * 16 + grp) * ROWPAD + k16 * 8 + tig;
                fa[mt][0] = ap[0];
                fa[mt][1] = ap[8 * ROWPAD];
                fa[mt][2] = ap[4];
                fa[mt][3] = ap[8 * ROWPAD + 4];
            }
#pragma unroll
            for (int nt = 0; nt < 8; nt++) {
                const uint32_t* bp = Bs + (wn * 64 + nt * 8 + grp) * ROWPAD + k16 * 8 + tig;
                fb[nt][0] = bp[0];
                fb[nt][1] = bp[4];
            }
#pragma unroll
            for (int nt = 0; nt < 8; nt++)
#pragma unroll
                for (int mt = 0; mt < 2; mt++)
                    mma_f16(acc[mt][nt], fa[mt], fb[nt]);
        }
        __syncthreads();
    }

    // ---- epilogue ----
    // Row stats: thread's rows = i0 + wm*32 + mt*16 + grp + h*8
#pragma unroll
    for (int mt = 0; mt < 2; mt++) {
#pragma unroll
        for (int h = 0; h < 2; h++) {
            const int rin = wm * 32 + mt * 16 + grp + h * 8;
            const int gi = i0 + rin;
            const float dr = smem[DIAGR_OFF + rin];
            int cnt = 0;
            float rmax = 0.0f;
#pragma unroll
            for (int nt = 0; nt < 8; nt++) {
#pragma unroll
                for (int e = 0; e < 2; e++) {
                    const int cin = wn * 64 + nt * 8 + 2 * tig + e;
                    float v = acc[mt][nt][h * 2 + e];
                    bool od = (gi != j0 + cin);
                    cnt += (od && (v < dr));
                    if (od) rmax = fmaxf(rmax, (MARGIN + v) - dr);
                }
            }
            cnt  += __shfl_xor_sync(FULLW, cnt, 1);
            rmax  = fmaxf(rmax, __shfl_xor_sync(FULLW, rmax, 1));
            cnt  += __shfl_xor_sync(FULLW, cnt, 2);
            rmax  = fmaxf(rmax, __shfl_xor_sync(FULLW, rmax, 2));
            if (tig == 0) {
                atomicAdd(&sRCnt[rin], cnt);
                atomicMax(&sRMax[rin], __float_as_int(rmax));
            }
        }
    }
    // Col stats: thread's cols = j0 + wn*64 + nt*8 + 2*tig + e
#pragma unroll
    for (int nt = 0; nt < 8; nt++) {
#pragma unroll
        for (int e = 0; e < 2; e++) {
            const int cin = wn * 64 + nt * 8 + 2 * tig + e;
            const float dc = smem[DIAGC_OFF + cin];
            int cnt = 0;
            float cmax = 0.0f;
#pragma unroll
            for (int mt = 0; mt < 2; mt++) {
#pragma unroll
                for (int h = 0; h < 2; h++) {
                    const int gi = i0 + wm * 32 + mt * 16 + grp + h * 8;
                    float v = acc[mt][nt][h * 2 + e];
                    bool od = (gi != j0 + cin);
                    cnt += (od && (v < dc));
                    if (od) cmax = fmaxf(cmax, (MARGIN + v) - dc);
                }
            }
            cnt  += __shfl_xor_sync(FULLW, cnt, 4);
            cmax  = fmaxf(cmax, __shfl_xor_sync(FULLW, cmax, 4));
            cnt  += __shfl_xor_sync(FULLW, cnt, 8);
            cmax  = fmaxf(cmax, __shfl_xor_sync(FULLW, cmax, 8));
            cnt  += __shfl_xor_sync(FULLW, cnt, 16);
            cmax  = fmaxf(cmax, __shfl_xor_sync(FULLW, cmax, 16));
            if (grp == 0) {
                atomicAdd(&sCCnt[cin], cnt);
                atomicMax(&sCMax[cin], __float_as_int(cmax));
            }
        }
    }
    __syncthreads();

    if (tid < 128) {
        atomicAdd(&g_rank1[i0 + tid], sRCnt[tid]);
        atomicMax(&g_rowcost[i0 + tid], sRMax[tid]);
        atomicAdd(&g_rank2[j0 + tid], sCCnt[tid]);
        atomicMax(&g_colcost[j0 + tid], sCMax[tid]);
    }
}

// ---------------------------------------------------------------------------
// Deterministic final reduction
// ---------------------------------------------------------------------------
__global__ void final_kernel(float* out, int n) {
    __shared__ float red[32];
    const int t = threadIdx.x;
    const int nv = n / 4;
    float sum = 0.0f;
#pragma unroll
    for (int v = 0; v < 2; v++) {
        int i = t + v * 1024;
        if (i < nv) {
            int4 r1 = ((const int4*)g_rank1)[i];
            int4 r2 = ((const int4*)g_rank2)[i];
            int4 rc = ((const int4*)g_rowcost)[i];
            int4 cc = ((const int4*)g_colcost)[i];
            sum += __int_as_float(rc.x) / ((float)r1.x + 1.0f)
                 + __int_as_float(rc.y) / ((float)r1.y + 1.0f)
                 + __int_as_float(rc.z) / ((float)r1.z + 1.0f)
                 + __int_as_float(rc.w) / ((float)r1.w + 1.0f)
                 + __int_as_float(cc.x) / ((float)r2.x + 1.0f)
                 + __int_as_float(cc.y) / ((float)r2.y + 1.0f)
                 + __int_as_float(cc.z) / ((float)r2.z + 1.0f)
                 + __int_as_float(cc.w) / ((float)r2.w + 1.0f);
        }
    }
#pragma unroll
    for (int o = 16; o > 0; o >>= 1) sum += __shfl_xor_sync(FULLW, sum, o);
    if ((t & 31) == 0) red[t >> 5] = sum;
    __syncthreads();
    if (t < 32) {
        float v = red[t];
#pragma unroll
        for (int o = 16; o > 0; o >>= 1) v += __shfl_xor_sync(FULLW, v, o);
        if (t == 0) out[0] = v;
    }
}

// ---------------------------------------------------------------------------
extern "C" void kernel_launch(void* const* d_in, const int* in_sizes, int n_in,
                              void* d_out, int out_size) {
    const float* im = (const float*)d_in[0];
    const float* s  = (const float*)d_in[1];
    float* out = (float*)d_out;
    const int n = in_sizes[0] / D;   // 8192

    cudaFuncSetAttribute(tile_kernel,
                         cudaFuncAttributeMaxDynamicSharedMemorySize, SMEM_BYTES);

    init_kernel<<<(n + 255) / 256, 256>>>(out, n);
    conv_kernel<<<(n * (D / 4) + 255) / 256, 256>>>(im, s);
    diag_kernel<<<(n * 32 + 255) / 256, 256>>>(im, s, n);
    dim3 grid(n / BN, n / BM);
    tile_kernel<<<grid, 256, SMEM_BYTES>>>();
    final_kernel<<<1, 1024>>>(out, n);
}

// round 13
// speedup vs baseline: 6.0197x; 1.0467x over previous
#include <cuda_runtime.h>
#include <cuda_fp16.h>
#include <cstdint>

#define NMAX 8192
#define D 256
#define MARGIN 0.2f
#define FULLW 0xFFFFFFFFu

// ---------------------------------------------------------------------------
// Scratch (allocation-free rule: __device__ globals)
// ---------------------------------------------------------------------------
__device__ float  g_diag[NMAX];
__device__ int    g_rank1[NMAX];
__device__ int    g_rank2[NMAX];
__device__ int    g_rowcost[NMAX];   // float bits, values >= 0
__device__ int    g_colcost[NMAX];   // float bits, values >= 0
__device__ __half g_Ah[NMAX * D];    // 4.2 MB
__device__ __half g_Bh[NMAX * D];    // 4.2 MB

// ---------------------------------------------------------------------------
// helpers
// ---------------------------------------------------------------------------
__device__ __forceinline__ uint32_t smem_u32(const void* p) {
    uint32_t a;
    asm("{ .reg .u64 t; cvta.to.shared.u64 t, %1; cvt.u32.u64 %0, t; }"
        : "=r"(a) : "l"(p));
    return a;
}
__device__ __forceinline__ void cp16(uint32_t dst, const void* src) {
    asm volatile("cp.async.cg.shared.global [%0], [%1], 16;"
                 :: "r"(dst), "l"(src));
}
__device__ __forceinline__ void mma_f16(float* d, const uint32_t* a, const uint32_t* b) {
    asm volatile(
        "mma.sync.aligned.m16n8k16.row.col.f32.f16.f16.f32 "
        "{%0,%1,%2,%3}, {%4,%5,%6,%7}, {%8,%9}, {%0,%1,%2,%3};"
        : "+f"(d[0]), "+f"(d[1]), "+f"(d[2]), "+f"(d[3])
        : "r"(a[0]), "r"(a[1]), "r"(a[2]), "r"(a[3]), "r"(b[0]), "r"(b[1]));
}
__device__ __forceinline__ uint32_t h2pack(float x, float y) {
    __half2 h = __floats2half2_rn(x, y);
    return *(uint32_t*)&h;
}

// ---------------------------------------------------------------------------
// prep: fused init + fp16 convert + diagonal. One warp per row.
// Each lane owns 8 consecutive floats of the row (lane*8 .. lane*8+7).
// ---------------------------------------------------------------------------
__global__ void prep_kernel(const float* __restrict__ im,
                            const float* __restrict__ s,
                            float* out, int n) {
    int warp = (blockIdx.x * blockDim.x + threadIdx.x) >> 5;
    int lane = threadIdx.x & 31;
    if (warp >= n) return;

    size_t base = (size_t)warp * D + lane * 8;
    float4 a0 = *(const float4*)(im + base);
    float4 a1 = *(const float4*)(im + base + 4);
    float4 b0 = *(const float4*)(s + base);
    float4 b1 = *(const float4*)(s + base + 4);

    // fp16 copies
    *(uint2*)(g_Ah + base)     = make_uint2(h2pack(a0.x, a0.y), h2pack(a0.z, a0.w));
    *(uint2*)(g_Ah + base + 4) = make_uint2(h2pack(a1.x, a1.y), h2pack(a1.z, a1.w));
    *(uint2*)(g_Bh + base)     = make_uint2(h2pack(b0.x, b0.y), h2pack(b0.z, b0.w));
    *(uint2*)(g_Bh + base + 4) = make_uint2(h2pack(b1.x, b1.y), h2pack(b1.z, b1.w));

    // diagonal in exact fp32
    float acc = a0.x * b0.x + a0.y * b0.y + a0.z * b0.z + a0.w * b0.w
              + a1.x * b1.x + a1.y * b1.y + a1.z * b1.z + a1.w * b1.w;
#pragma unroll
    for (int o = 16; o > 0; o >>= 1) acc += __shfl_xor_sync(FULLW, acc, o);

    if (lane == 0) {
        g_diag[warp] = acc;
        g_rank1[warp] = 0; g_rank2[warp] = 0;
        g_rowcost[warp] = 0; g_colcost[warp] = 0;
        if (warp == 0) out[0] = 0.0f;
    }
}

// ---------------------------------------------------------------------------
// Fused mma.sync fp16 tile kernel: 128x128 score tile per CTA.
// 256 threads / 8 warps (4 M x 2 N), warp tile 32x64, m16n8k16,
// K=256 halves, BK=64 halves, double-buffered cp.async, ONE sync per stage:
//   wait_group 0 -> __syncthreads -> prefetch st+1 (other buf) -> compute.
// The top sync also retires the previous stage's compute, so overwriting
// the other buffer is safe. 2 CTAs/SM. ROWPAD=36: conflict-free LDS.
// ---------------------------------------------------------------------------
#define BM 128
#define BN 128
#define BK 64                    // halves per row per stage (128 B)
#define ROWPAD 36                // uint32 words per row (32 data + 4 pad)
#define NSTAGE (D / BK)          // 4
#define AS_WORDS (BM * ROWPAD)   // 4608 per stage
#define BS_WORDS (BN * ROWPAD)   // 4608 per stage
#define AS_OFF 0
#define BS_OFF (2 * AS_WORDS)                 // 9216
#define DIAGR_OFF (BS_OFF + 2 * BS_WORDS)     // 18432
#define DIAGC_OFF (DIAGR_OFF + 128)
#define RCNT_OFF  (DIAGC_OFF + 128)
#define RMAX_OFF  (RCNT_OFF + 128)
#define CCNT_OFF  (RMAX_OFF + 128)
#define CMAX_OFF  (CCNT_OFF + 128)
#define SMEM_WORDS (CMAX_OFF + 128)           // 19200
#define SMEM_BYTES (SMEM_WORDS * 4)           // 76800

__global__ __launch_bounds__(256, 2)
void tile_kernel() {
    extern __shared__ __align__(16) float smem[];
    uint32_t* smu = (uint32_t*)smem;
    int* sRCnt = (int*)(smem + RCNT_OFF);
    int* sRMax = (int*)(smem + RMAX_OFF);
    int* sCCnt = (int*)(smem + CCNT_OFF);
    int* sCMax = (int*)(smem + CMAX_OFF);

    const int tid  = threadIdx.x;
    const int wid  = tid >> 5;
    const int lane = tid & 31;
    const int wm   = wid >> 1;          // 0..3 -> M offset wm*32
    const int wn   = wid & 1;           // 0..1 -> N offset wn*64
    const int grp  = lane >> 2;         // 0..7
    const int tig  = lane & 3;          // 0..3
    const int i0 = blockIdx.y * BM;
    const int j0 = blockIdx.x * BN;
    const uint32_t sb = smem_u32(smem);

    if (tid < 128) {
        smem[DIAGR_OFF + tid] = g_diag[i0 + tid];
        smem[DIAGC_OFF + tid] = g_diag[j0 + tid];
        sRCnt[tid] = 0; sRMax[tid] = 0;
        sCCnt[tid] = 0; sCMax[tid] = 0;
    }

    float acc[2][8][4];
#pragma unroll
    for (int mt = 0; mt < 2; mt++)
#pragma unroll
        for (int nt = 0; nt < 8; nt++)
#pragma unroll
            for (int e = 0; e < 4; e++) acc[mt][nt][e] = 0.0f;

    // staging: 16B = 8 halves per cp.async; row stage = 64 halves = 8 chunks
    const int ldrow = tid >> 3;         // 0..31 base row
    const int ldch  = tid & 7;          // chunk within row
    const __half* Abase = g_Ah + (size_t)(i0 + ldrow) * D + ldch * 8;
    const __half* Bbase = g_Bh + (size_t)(j0 + ldrow) * D + ldch * 8;

    // ---- prologue: stage 0 ----
    {
        uint32_t adst = sb + (AS_OFF + ldrow * ROWPAD + ldch * 4) * 4;
        uint32_t bdst = sb + (BS_OFF + ldrow * ROWPAD + ldch * 4) * 4;
#pragma unroll
        for (int q = 0; q < 4; q++)      // A: 128 rows, 32 apart
            cp16(adst + q * 32 * ROWPAD * 4, Abase + (size_t)(q * 32) * D);
#pragma unroll
        for (int q = 0; q < 4; q++)      // B: 128 rows
            cp16(bdst + q * 32 * ROWPAD * 4, Bbase + (size_t)(q * 32) * D);
        asm volatile("cp.async.commit_group;");
    }

#pragma unroll
    for (int st = 0; st < NSTAGE; st++) {
        const int cur = st & 1;
        asm volatile("cp.async.wait_group 0;");
        __syncthreads();    // stage st data visible + prior compute retired

        if (st + 1 < NSTAGE) {
            const int nxt = (st + 1) & 1;
            uint32_t adst = sb + (AS_OFF + nxt * AS_WORDS + ldrow * ROWPAD + ldch * 4) * 4;
            uint32_t bdst = sb + (BS_OFF + nxt * BS_WORDS + ldrow * ROWPAD + ldch * 4) * 4;
            const __half* as = Abase + (st + 1) * BK;
            const __half* bs = Bbase + (st + 1) * BK;
#pragma unroll
            for (int q = 0; q < 4; q++)
                cp16(adst + q * 32 * ROWPAD * 4, as + (size_t)(q * 32) * D);
#pragma unroll
            for (int q = 0; q < 4; q++)
                cp16(bdst + q * 32 * ROWPAD * 4, bs + (size_t)(q * 32) * D);
            asm volatile("cp.async.commit_group;");
        }

        const uint32_t* As = smu + AS_OFF + cur * AS_WORDS;
        const uint32_t* Bs = smu + BS_OFF + cur * BS_WORDS;
#pragma unroll
        for (int k16 = 0; k16 < BK / 16; k16++) {
            uint32_t fa[2][4], fb[8][2];
#pragma unroll
            for (int mt = 0; mt < 2; mt++) {
                const uint32_t* ap = As + (wm * 32 + mt * 16 + grp) * ROWPAD + k16 * 8 + tig;
                fa[mt][0] = ap[0];
                fa[mt][1] = ap[8 * ROWPAD];
                fa[mt][2] = ap[4];
                fa[mt][3] = ap[8 * ROWPAD + 4];
            }
#pragma unroll
            for (int nt = 0; nt < 8; nt++) {
                const uint32_t* bp = Bs + (wn * 64 + nt * 8 + grp) * ROWPAD + k16 * 8 + tig;
                fb[nt][0] = bp[0];
                fb[nt][1] = bp[4];
            }
#pragma unroll
            for (int nt = 0; nt < 8; nt++)
#pragma unroll
                for (int mt = 0; mt < 2; mt++)
                    mma_f16(acc[mt][nt], fa[mt], fb[nt]);
        }
    }
    __syncthreads();   // retire last stage's compute before epilogue atomics

    // ---- epilogue ----
    // Row stats: thread's rows = i0 + wm*32 + mt*16 + grp + h*8
#pragma unroll
    for (int mt = 0; mt < 2; mt++) {
#pragma unroll
        for (int h = 0; h < 2; h++) {
            const int rin = wm * 32 + mt * 16 + grp + h * 8;
            const int gi = i0 + rin;
            const float dr = smem[DIAGR_OFF + rin];
            int cnt = 0;
            float rmax = 0.0f;
#pragma unroll
            for (int nt = 0; nt < 8; nt++) {
#pragma unroll
                for (int e = 0; e < 2; e++) {
                    const int cin = wn * 64 + nt * 8 + 2 * tig + e;
                    float v = acc[mt][nt][h * 2 + e];
                    bool od = (gi != j0 + cin);
                    cnt += (od && (v < dr));
                    if (od) rmax = fmaxf(rmax, (MARGIN + v) - dr);
                }
            }
            cnt  += __shfl_xor_sync(FULLW, cnt, 1);
            rmax  = fmaxf(rmax, __shfl_xor_sync(FULLW, rmax, 1));
            cnt  += __shfl_xor_sync(FULLW, cnt, 2);
            rmax  = fmaxf(rmax, __shfl_xor_sync(FULLW, rmax, 2));
            if (tig == 0) {
                atomicAdd(&sRCnt[rin], cnt);
                atomicMax(&sRMax[rin], __float_as_int(rmax));
            }
        }
    }
    // Col stats: thread's cols = j0 + wn*64 + nt*8 + 2*tig + e
#pragma unroll
    for (int nt = 0; nt < 8; nt++) {
#pragma unroll
        for (int e = 0; e < 2; e++) {
            const int cin = wn * 64 + nt * 8 + 2 * tig + e;
            const float dc = smem[DIAGC_OFF + cin];
            int cnt = 0;
            float cmax = 0.0f;
#pragma unroll
            for (int mt = 0; mt < 2; mt++) {
#pragma unroll
                for (int h = 0; h < 2; h++) {
                    const int gi = i0 + wm * 32 + mt * 16 + grp + h * 8;
                    float v = acc[mt][nt][h * 2 + e];
                    bool od = (gi != j0 + cin);
                    cnt += (od && (v < dc));
                    if (od) cmax = fmaxf(cmax, (MARGIN + v) - dc);
                }
            }
            cnt  += __shfl_xor_sync(FULLW, cnt, 4);
            cmax  = fmaxf(cmax, __shfl_xor_sync(FULLW, cmax, 4));
            cnt  += __shfl_xor_sync(FULLW, cnt, 8);
            cmax  = fmaxf(cmax, __shfl_xor_sync(FULLW, cmax, 8));
            cnt  += __shfl_xor_sync(FULLW, cnt, 16);
            cmax  = fmaxf(cmax, __shfl_xor_sync(FULLW, cmax, 16));
            if (grp == 0) {
                atomicAdd(&sCCnt[cin], cnt);
                atomicMax(&sCMax[cin], __float_as_int(cmax));
            }
        }
    }
    __syncthreads();

    if (tid < 128) {
        atomicAdd(&g_rank1[i0 + tid], sRCnt[tid]);
        atomicMax(&g_rowcost[i0 + tid], sRMax[tid]);
        atomicAdd(&g_rank2[j0 + tid], sCCnt[tid]);
        atomicMax(&g_colcost[j0 + tid], sCMax[tid]);
    }
}

// ---------------------------------------------------------------------------
// Deterministic final reduction
// ---------------------------------------------------------------------------
__global__ void final_kernel(float* out, int n) {
    __shared__ float red[32];
    const int t = threadIdx.x;
    const int nv = n / 4;
    float sum = 0.0f;
#pragma unroll
    for (int v = 0; v < 2; v++) {
        int i = t + v * 1024;
        if (i < nv) {
            int4 r1 = ((const int4*)g_rank1)[i];
            int4 r2 = ((const int4*)g_rank2)[i];
            int4 rc = ((const int4*)g_rowcost)[i];
            int4 cc = ((const int4*)g_colcost)[i];
            sum += __int_as_float(rc.x) / ((float)r1.x + 1.0f)
                 + __int_as_float(rc.y) / ((float)r1.y + 1.0f)
                 + __int_as_float(rc.z) / ((float)r1.z + 1.0f)
                 + __int_as_float(rc.w) / ((float)r1.w + 1.0f)
                 + __int_as_float(cc.x) / ((float)r2.x + 1.0f)
                 + __int_as_float(cc.y) / ((float)r2.y + 1.0f)
                 + __int_as_float(cc.z) / ((float)r2.z + 1.0f)
                 + __int_as_float(cc.w) / ((float)r2.w + 1.0f);
        }
    }
#pragma unroll
    for (int o = 16; o > 0; o >>= 1) sum += __shfl_xor_sync(FULLW, sum, o);
    if ((t & 31) == 0) red[t >> 5] = sum;
    __syncthreads();
    if (t < 32) {
        float v = red[t];
#pragma unroll
        for (int o = 16; o > 0; o >>= 1) v += __shfl_xor_sync(FULLW, v, o);
        if (t == 0) out[0] = v;
    }
}

// ---------------------------------------------------------------------------
extern "C" void kernel_launch(void* const* d_in, const int* in_sizes, int n_in,
                              void* d_out, int out_size) {
    const float* im = (const float*)d_in[0];
    const float* s  = (const float*)d_in[1];
    float* out = (float*)d_out;
    const int n = in_sizes[0] / D;   // 8192

    cudaFuncSetAttribute(tile_kernel,
                         cudaFuncAttributeMaxDynamicSharedMemorySize, SMEM_BYTES);

    prep_kernel<<<(n * 32 + 255) / 256, 256>>>(im, s, out, n);
    dim3 grid(n / BN, n / BM);
    tile_kernel<<<grid, 256, SMEM_BYTES>>>();
    final_kernel<<<1, 1024>>>(out, n);
}